// round 1
// baseline (speedup 1.0000x reference)
#include <cuda_runtime.h>
#include <math.h>
#include <stdint.h>

// NGP multiresolution hash-grid interpolation encoding.
// B=262144 points, DIM=3, L=16 levels, T=19 (2^19 entries/level), F=2 features.
// out[b, l*2+f] = sum_{v=0..7} w_v * tables[l, hash(corner_v) & MASK, f]

#define NGP_L 16
#define NGP_T 19
#define NGP_MASK ((1u << NGP_T) - 1u)
#define NGP_P1 2654435761u
#define NGP_P2 805459861u

struct ResParams { float r[NGP_L]; };

__global__ void __launch_bounds__(256, 8) ngp_enc_kernel(
    const float* __restrict__ x,
    const float2* __restrict__ tables,
    float2* __restrict__ out,
    ResParams rp, int npts)
{
    int t = blockIdx.x * 256 + threadIdx.x;
    int b = t >> 4;
    int l = t & 15;
    if (b >= npts) return;

    float res = rp.r[l];

    float x0 = __ldg(x + 3 * b + 0);
    float x1 = __ldg(x + 3 * b + 1);
    float x2 = __ldg(x + 3 * b + 2);

    float sx = x0 * res;
    float sy = x1 * res;
    float sz = x2 * res;

    float fx = floorf(sx);
    float fy = floorf(sy);
    float fz = floorf(sz);

    unsigned gx = (unsigned)fx;
    unsigned gy = (unsigned)fy;
    unsigned gz = (unsigned)fz;

    float tx = sx - fx;
    float ty = sy - fy;
    float tz = sz - fz;

    // hash partials: dim0 prime = 1
    unsigned hx0 = gx;
    unsigned hx1 = gx + 1u;
    unsigned hy0 = gy * NGP_P1;
    unsigned hy1 = hy0 + NGP_P1;
    unsigned hz0 = gz * NGP_P2;
    unsigned hz1 = hz0 + NGP_P2;

    const float2* __restrict__ tbl = tables + ((size_t)l << NGP_T);

    // 8 corner indices (corner v: bit0->x, bit1->y, bit2->z)
    unsigned i0 = (hx0 ^ hy0 ^ hz0) & NGP_MASK;
    unsigned i1 = (hx1 ^ hy0 ^ hz0) & NGP_MASK;
    unsigned i2 = (hx0 ^ hy1 ^ hz0) & NGP_MASK;
    unsigned i3 = (hx1 ^ hy1 ^ hz0) & NGP_MASK;
    unsigned i4 = (hx0 ^ hy0 ^ hz1) & NGP_MASK;
    unsigned i5 = (hx1 ^ hy0 ^ hz1) & NGP_MASK;
    unsigned i6 = (hx0 ^ hy1 ^ hz1) & NGP_MASK;
    unsigned i7 = (hx1 ^ hy1 ^ hz1) & NGP_MASK;

    // batch the 8 gathers for MLP=8 (hide L2 latency)
    float2 v0 = __ldg(tbl + i0);
    float2 v1 = __ldg(tbl + i1);
    float2 v2 = __ldg(tbl + i2);
    float2 v3 = __ldg(tbl + i3);
    float2 v4 = __ldg(tbl + i4);
    float2 v5 = __ldg(tbl + i5);
    float2 v6 = __ldg(tbl + i6);
    float2 v7 = __ldg(tbl + i7);

    float wx0 = 1.0f - tx;
    float wy0 = 1.0f - ty;
    float wz0 = 1.0f - tz;

    float w00 = wx0 * wy0;   // x0 y0
    float w10 = tx  * wy0;   // x1 y0
    float w01 = wx0 * ty;    // x0 y1
    float w11 = tx  * ty;    // x1 y1

    float a0 = 0.0f, a1 = 0.0f;
    float w;
    w = w00 * wz0; a0 = fmaf(w, v0.x, a0); a1 = fmaf(w, v0.y, a1);
    w = w10 * wz0; a0 = fmaf(w, v1.x, a0); a1 = fmaf(w, v1.y, a1);
    w = w01 * wz0; a0 = fmaf(w, v2.x, a0); a1 = fmaf(w, v2.y, a1);
    w = w11 * wz0; a0 = fmaf(w, v3.x, a0); a1 = fmaf(w, v3.y, a1);
    w = w00 * tz;  a0 = fmaf(w, v4.x, a0); a1 = fmaf(w, v4.y, a1);
    w = w10 * tz;  a0 = fmaf(w, v5.x, a0); a1 = fmaf(w, v5.y, a1);
    w = w01 * tz;  a0 = fmaf(w, v6.x, a0); a1 = fmaf(w, v6.y, a1);
    w = w11 * tz;  a0 = fmaf(w, v7.x, a0); a1 = fmaf(w, v7.y, a1);

    out[(size_t)b * 16 + l] = make_float2(a0, a1);
}

extern "C" void kernel_launch(void* const* d_in, const int* in_sizes, int n_in,
                              void* d_out, int out_size)
{
    const float* x = (const float*)d_in[0];
    const float2* tables = (const float2*)d_in[1];
    float2* out = (float2*)d_out;
    int npts = in_sizes[0] / 3;

    // Replicate numpy's RES computation bit-for-bit in float64 using the same
    // glibc libm the reference uses on this host (incl. numpy's pow shortcuts
    // for small integer exponents). RES sits exactly on integers at levels
    // 0,3,6,9,12,15 so hardcoding risks off-by-one in floor().
    ResParams rp;
    double bb = exp((log(512.0) - log(16.0)) / 15.0);
    for (int l = 0; l < NGP_L; l++) {
        double p;
        if (l == 0)      p = 1.0;
        else if (l == 1) p = bb;
        else if (l == 2) p = bb * bb;     // numpy npy_pow shortcut y==2 -> x*x
        else             p = pow(bb, (double)l);
        rp.r[l] = (float)floor(16.0 * p);
    }

    int total = npts * 16;
    int blocks = (total + 255) / 256;
    ngp_enc_kernel<<<blocks, 256>>>(x, tables, out, rp, npts);
}